// round 15
// baseline (speedup 1.0000x reference)
#include <cuda_runtime.h>
#include <cuda_fp16.h>
#include <math.h>
#include <stdint.h>

// Problem shape: B=4, S=4096, D=1024, H=64
#define B_ 4
#define S_ 4096
#define D_ 1024
#define H_ 64
#define NROWS (B_ * S_)   // 16384

// Attention operands (fp16). Q pre-scaled by C = 0.125*log2(e) so the QK mma
// directly emits the exp2 argument. K, V unscaled.
__device__ __half g_qh[NROWS * H_];
__device__ __half g_kh[NROWS * H_];
__device__ __half g_vh[NROWS * H_];
// Pre-converted W (fp16), per-64k-chunk swizzled tiles (8KB per chunk).
__device__ __half g_wh[3][D_ * H_];
// Pre-converted X (fp16), per (row-tile, k-chunk) swizzled tiles (16KB each).
__device__ __half g_xh[NROWS * D_];

#define EXPC 0.18033688f   // 0.125 * log2(e)

// ===========================================================================
// helpers
// ===========================================================================
__device__ __forceinline__ uint32_t smem_u32(const void* p) {
    uint32_t a;
    asm("{ .reg .u64 t; cvta.to.shared.u64 t, %1; cvt.u32.u64 %0, t; }" : "=r"(a) : "l"(p));
    return a;
}
__device__ __forceinline__ uint32_t packhf(float a, float b) {
    uint32_t r;
    asm("cvt.rn.f16x2.f32 %0, %2, %1;" : "=r"(r) : "f"(a), "f"(b));
    return r;
}
__device__ __forceinline__ uint32_t ex2h2(uint32_t x) {
    uint32_t r;
    asm("ex2.approx.f16x2 %0, %1;" : "=r"(r) : "r"(x));
    return r;
}

__device__ __forceinline__ void ldsm4(uint32_t& r0, uint32_t& r1, uint32_t& r2, uint32_t& r3, uint32_t addr) {
    asm volatile("ldmatrix.sync.aligned.m8n8.x4.shared.b16 {%0,%1,%2,%3}, [%4];"
        : "=r"(r0), "=r"(r1), "=r"(r2), "=r"(r3) : "r"(addr));
}
__device__ __forceinline__ void ldsm4t(uint32_t& r0, uint32_t& r1, uint32_t& r2, uint32_t& r3, uint32_t addr) {
    asm volatile("ldmatrix.sync.aligned.m8n8.x4.trans.shared.b16 {%0,%1,%2,%3}, [%4];"
        : "=r"(r0), "=r"(r1), "=r"(r2), "=r"(r3) : "r"(addr));
}
__device__ __forceinline__ void mma16816h(float& d0, float& d1, float& d2, float& d3,
                                           uint32_t a0, uint32_t a1, uint32_t a2, uint32_t a3,
                                           uint32_t b0, uint32_t b1) {
    asm volatile("mma.sync.aligned.m16n8k16.row.col.f32.f16.f16.f32 "
        "{%0,%1,%2,%3}, {%4,%5,%6,%7}, {%8,%9}, {%0,%1,%2,%3};"
        : "+f"(d0), "+f"(d1), "+f"(d2), "+f"(d3)
        : "r"(a0), "r"(a1), "r"(a2), "r"(a3), "r"(b0), "r"(b1));
}

#define CP_ASYNC16(dst, src) \
    asm volatile("cp.async.cg.shared.global [%0], [%1], 16;" :: "r"(dst), "l"(src))
#define CP_COMMIT() asm volatile("cp.async.commit_group;" ::: "memory")
#define CP_WAIT(n)  asm volatile("cp.async.wait_group %0;" :: "n"(n) : "memory")

// ===========================================================================
// Kernel 0: convert X and W to fp16 swizzled tiles (memory-bound).
// Blocks 0..2047: X tiles (mt = blk>>4, ck = blk&15), 16KB each.
// Blocks 2048..2095: W tiles (m = (blk-2048)/16, ck = (blk-2048)&15), 8KB each.
// ===========================================================================
__global__ __launch_bounds__(256) void conv_xw_kernel(
    const float* __restrict__ X,
    const float* __restrict__ Wq, const float* __restrict__ Wk, const float* __restrict__ Wv)
{
    const int blk = blockIdx.x, tid = threadIdx.x;
    if (blk < 2048) {
        const int mt = blk >> 4, ck = blk & 15;
        const float4* X4 = (const float4*)X;
        char* dst = (char*)g_xh + (size_t)blk * 16384;      // 16KB per X tile
        #pragma unroll
        for (int j = 0; j < 8; j++) {
            int f = tid + j * 256;                  // 0..2047 float4
            int r = f >> 4, c4 = f & 15;
            float4 v = X4[(size_t)(mt * 128 + r) * 256 + ck * 16 + c4];
            uint32_t so = (uint32_t)(r * 128 + (((c4 >> 1) ^ (r & 7)) << 4) + (c4 & 1) * 8);
            *(uint32_t*)(dst + so)     = packhf(v.x, v.y);
            *(uint32_t*)(dst + so + 4) = packhf(v.z, v.w);
        }
    } else {
        const int c2 = blk - 2048;
        const int m = c2 >> 4, ck = c2 & 15;
        const float4* W4 = (const float4*)((m == 0) ? Wq : ((m == 1) ? Wk : Wv));
        char* dst = (char*)g_wh[m] + ck * 8192;
        #pragma unroll
        for (int j = 0; j < 4; j++) {
            int f = tid + j * 256;
            int r = f >> 4, c4 = f & 15;
            float4 v = W4[(size_t)(ck * 64 + r) * 16 + c4];
            uint32_t so = (uint32_t)(r * 128 + (((c4 >> 1) ^ (r & 7)) << 4) + (c4 & 1) * 8);
            *(uint32_t*)(dst + so)     = packhf(v.x, v.y);
            *(uint32_t*)(dst + so + 4) = packhf(v.z, v.w);
        }
    }
}

// ===========================================================================
// Kernel 1: fused QKV projection + LayerNorm. Pure cp.async double-buffered
// pipeline (X and W pre-converted).
// Stage layout (40KB): [X 16KB][W0 8KB][W1 8KB][W2 8KB]; 2 stages = 80KB.
// ===========================================================================
#define P_STAGE 40960
#define P_W0    16384
#define PROJ_SMEM (2 * P_STAGE)
#define P_NK 16

__global__ __launch_bounds__(256) void proj_ln_kernel()
{
    extern __shared__ char smem[];
    const uint32_t sb = smem_u32(smem);
    const int tid  = threadIdx.x;
    const int warp = tid >> 5, lane = tid & 31;
    const int wrow = warp * 16;
    const int mt   = blockIdx.x;

    float a0[3][8], a1[3][8], a2[3][8], a3[3][8];
    #pragma unroll
    for (int m = 0; m < 3; m++)
        #pragma unroll
        for (int nc = 0; nc < 8; nc++) { a0[m][nc]=0.f; a1[m][nc]=0.f; a2[m][nc]=0.f; a3[m][nc]=0.f; }

    const int arow = wrow + (lane & 15);
    const int as7  = arow & 7;
    const int abit = lane >> 4;
    const int krv  = lane & 15;
    const int vbit = lane >> 4;
    const int s7   = lane & 7;

    const char* xB = (const char*)g_xh + (size_t)mt * 16 * 16384;

    // prefetch stage 0: X chunk 0 (16KB, 4/thread) + W chunk 0 x3 (8KB, 2/thread each)
    {
        int f16 = tid * 16;
        #pragma unroll
        for (int j = 0; j < 4; j++) {
            int o = f16 + j * 4096;                  // 0..16383
            CP_ASYNC16(sb + o, xB + o);
        }
        #pragma unroll
        for (int j = 0; j < 2; j++) {
            int o = f16 + j * 4096;                  // 0..8191
            CP_ASYNC16(sb + P_W0         + o, (const char*)g_wh[0] + o);
            CP_ASYNC16(sb + P_W0 + 8192  + o, (const char*)g_wh[1] + o);
            CP_ASYNC16(sb + P_W0 + 16384 + o, (const char*)g_wh[2] + o);
        }
        CP_COMMIT();
    }

    for (int kt = 0; kt < P_NK; kt++) {
        __syncthreads();
        if (kt + 1 < P_NK) {
            uint32_t dst = sb + ((kt + 1) & 1) * P_STAGE;
            size_t xo = (size_t)(kt + 1) * 16384;
            size_t wo = (size_t)(kt + 1) * 8192;
            int f16 = tid * 16;
            #pragma unroll
            for (int j = 0; j < 4; j++) {
                int o = f16 + j * 4096;
                CP_ASYNC16(dst + o, xB + xo + o);
            }
            #pragma unroll
            for (int j = 0; j < 2; j++) {
                int o = f16 + j * 4096;
                CP_ASYNC16(dst + P_W0         + o, (const char*)g_wh[0] + wo + o);
                CP_ASYNC16(dst + P_W0 + 8192  + o, (const char*)g_wh[1] + wo + o);
                CP_ASYNC16(dst + P_W0 + 16384 + o, (const char*)g_wh[2] + wo + o);
            }
            CP_COMMIT();
            CP_WAIT(1);
        } else {
            CP_WAIT(0);
        }
        __syncthreads();

        const uint32_t bufb = sb + (kt & 1) * P_STAGE;

        uint32_t xh[4][4];
        #pragma unroll
        for (int kc = 0; kc < 4; kc++) {
            int c16 = 2 * kc + abit;
            uint32_t ad = bufb + (uint32_t)(arow * 128) + ((c16 ^ as7) << 4);
            ldsm4(xh[kc][0], xh[kc][1], xh[kc][2], xh[kc][3], ad);
        }

        #pragma unroll
        for (int m = 0; m < 3; m++) {
            uint32_t wbase = bufb + P_W0 + (uint32_t)(m * 8192);
            #pragma unroll
            for (int kc = 0; kc < 4; kc++) {
                #pragma unroll
                for (int ncp = 0; ncp < 4; ncp++) {
                    uint32_t ad = wbase + (uint32_t)((kc * 16 + krv) * 128)
                                + (((2 * ncp + vbit) ^ s7) << 4);
                    uint32_t bh0, bh1, bh2, bh3;
                    ldsm4t(bh0, bh1, bh2, bh3, ad);
                    int n = 2 * ncp;
                    mma16816h(a0[m][n], a1[m][n], a2[m][n], a3[m][n],
                              xh[kc][0], xh[kc][1], xh[kc][2], xh[kc][3], bh0, bh1);
                    mma16816h(a0[m][n+1], a1[m][n+1], a2[m][n+1], a3[m][n+1],
                              xh[kc][0], xh[kc][1], xh[kc][2], xh[kc][3], bh2, bh3);
                }
            }
        }
    }

    const int rA = mt * 128 + wrow + (lane >> 2);
    const int rB = rA + 8;

    #pragma unroll
    for (int m = 0; m < 3; m++) {
        float mu0 = 0.f, mu1 = 0.f, rs0 = 1.f, rs1 = 1.f;
        if (m < 2) {
            float sum0 = 0.f, sum1 = 0.f;
            #pragma unroll
            for (int nc = 0; nc < 8; nc++) {
                sum0 += a0[m][nc] + a1[m][nc];
                sum1 += a2[m][nc] + a3[m][nc];
            }
            sum0 += __shfl_xor_sync(0xffffffffu, sum0, 1);
            sum0 += __shfl_xor_sync(0xffffffffu, sum0, 2);
            sum1 += __shfl_xor_sync(0xffffffffu, sum1, 1);
            sum1 += __shfl_xor_sync(0xffffffffu, sum1, 2);
            mu0 = sum0 * (1.0f / 64.0f);
            mu1 = sum1 * (1.0f / 64.0f);
            float v0 = 0.f, v1 = 0.f;
            #pragma unroll
            for (int nc = 0; nc < 8; nc++) {
                float d00 = a0[m][nc] - mu0, d01 = a1[m][nc] - mu0;
                float d10 = a2[m][nc] - mu1, d11 = a3[m][nc] - mu1;
                v0 += d00 * d00 + d01 * d01;
                v1 += d10 * d10 + d11 * d11;
            }
            v0 += __shfl_xor_sync(0xffffffffu, v0, 1);
            v0 += __shfl_xor_sync(0xffffffffu, v0, 2);
            v1 += __shfl_xor_sync(0xffffffffu, v1, 1);
            v1 += __shfl_xor_sync(0xffffffffu, v1, 2);
            rs0 = rsqrtf(v0 * (1.0f / 64.0f) + 1e-5f);
            rs1 = rsqrtf(v1 * (1.0f / 64.0f) + 1e-5f);
        }
        // fold exp2 constant into Q so attn's QK mma emits the ex2 argument
        if (m == 0) { rs0 *= EXPC; rs1 *= EXPC; }

        uint32_t* g32 = (uint32_t*)((m == 0) ? g_qh : ((m == 1) ? g_kh : g_vh));
        #pragma unroll
        for (int nc = 0; nc < 8; nc++) {
            uint32_t hA = packhf((a0[m][nc] - mu0) * rs0, (a1[m][nc] - mu0) * rs0);
            uint32_t hB = packhf((a2[m][nc] - mu1) * rs1, (a3[m][nc] - mu1) * rs1);
            size_t iA = (size_t)rA * 32 + nc * 4 + (lane & 3);
            size_t iB = (size_t)rB * 32 + nc * 4 + (lane & 3);
            g32[iA] = hA;
            g32[iB] = hB;
        }
    }
}

// ===========================================================================
// Kernel 2: flash attention, fp16 mma; ex2.approx.f16x2 softmax, l-sum via
// ones-B tensor mma. Fixed-reference softmax. (unchanged from R12/R13)
// ===========================================================================
#define OFF_KHI 0
#define OFF_VHI 16384
#define TB      32768
#define NT      (S_ / 128)
#define ATTN_SMEM (2 * TB)
#define ONESH2  0x3C003C00u   // fp16x2 {1.0, 1.0}

__global__ __launch_bounds__(256) void attn_mma_kernel(float* __restrict__ out)
{
    extern __shared__ char smem[];
    const uint32_t sb = smem_u32(smem);
    const int tid  = threadIdx.x;
    const int warp = tid >> 5, lane = tid & 31;
    const int wrow = warp * 16;

    const int qbase = blockIdx.x * 128;
    const int b     = qbase / S_;

    // ---- stage Q into buf0 (K area), grab A fragments ----
    {
        const uint4* qh4 = (const uint4*)((const char*)g_qh + (size_t)qbase * 128);
        #pragma unroll
        for (int j = 0; j < 4; j++) {
            int f = tid + j * 256;
            int r = f >> 3, c = f & 7;
            uint32_t so = r * 128 + ((c ^ (r & 7)) << 4);
            *(uint4*)(smem + OFF_KHI + so) = qh4[f];
        }
    }
    __syncthreads();

    uint32_t qh[4][4];
    {
        int arow = wrow + (lane & 15);
        int as7  = arow & 7;
        #pragma unroll
        for (int kc = 0; kc < 4; kc++) {
            int c16 = 2 * kc + (lane >> 4);
            uint32_t ad = sb + OFF_KHI + arow * 128 + ((c16 ^ as7) << 4);
            ldsm4(qh[kc][0], qh[kc][1], qh[kc][2], qh[kc][3], ad);
        }
    }
    __syncthreads();

    const char* khB = (const char*)g_kh + (size_t)(b * S_) * 128;
    const char* vhB = (const char*)g_vh + (size_t)(b * S_) * 128;

    // prefetch tile 0 -> buf 0
    {
        #pragma unroll
        for (int j = 0; j < 4; j++) {
            int f = tid + j * 256;
            int r = f >> 3, c = f & 7;
            uint32_t so = r * 128 + ((c ^ (r & 7)) << 4);
            int gs = f * 16;
            CP_ASYNC16(sb + OFF_KHI + so, khB + gs);
            CP_ASYNC16(sb + OFF_VHI + so, vhB + gs);
        }
        CP_COMMIT();
    }

    float s0[16], s1[16], s2[16], s3[16];
    float o0[8], o1[8], o2[8], o3[8];
    float la0 = 0.f, la1 = 0.f, la2 = 0.f, la3 = 0.f;   // l accumulators (ones-mma)
    #pragma unroll
    for (int i = 0; i < 8; i++) { o0[i] = 0.f; o1[i] = 0.f; o2[i] = 0.f; o3[i] = 0.f; }

    const int s7   = lane & 7;
    const int krq  = (lane & 7) + ((lane >> 4) << 3);
    const int cbit = (lane >> 3) & 1;
    const int krv  = lane & 15;
    const int vbit = lane >> 4;

    for (int kt = 0; kt < NT; kt++) {
        __syncthreads();

        if (kt + 1 < NT) {
            uint32_t dst = sb + ((kt + 1) & 1) * TB;
            size_t gb = (size_t)((kt + 1) * 128) * 128;
            #pragma unroll
            for (int j = 0; j < 4; j++) {
                int f = tid + j * 256;
                int r = f >> 3, c = f & 7;
                uint32_t so = r * 128 + ((c ^ (r & 7)) << 4);
                size_t gs = gb + f * 16;
                CP_ASYNC16(dst + OFF_KHI + so, khB + gs);
                CP_ASYNC16(dst + OFF_VHI + so, vhB + gs);
            }
            CP_COMMIT();
            CP_WAIT(1);
        } else {
            CP_WAIT(0);
        }
        __syncthreads();

        const uint32_t bufb = sb + (kt & 1) * TB;

        // ---- S' = Q' K^T  (Q pre-scaled; S' is the exp2 argument) ----
        #pragma unroll
        for (int i = 0; i < 16; i++) { s0[i] = 0.f; s1[i] = 0.f; s2[i] = 0.f; s3[i] = 0.f; }
        #pragma unroll
        for (int kc = 0; kc < 4; kc++) {
            #pragma unroll
            for (int ncp = 0; ncp < 8; ncp++) {
                uint32_t ad = bufb + OFF_KHI + (uint32_t)(ncp * 16 + krq) * 128
                            + (((2 * kc + cbit) ^ s7) << 4);
                uint32_t bh0, bh1, bh2, bh3;
                ldsm4(bh0, bh1, bh2, bh3, ad);
                int n = 2 * ncp;
                mma16816h(s0[n], s1[n], s2[n], s3[n], qh[kc][0], qh[kc][1], qh[kc][2], qh[kc][3], bh0, bh1);
                mma16816h(s0[n+1], s1[n+1], s2[n+1], s3[n+1], qh[kc][0], qh[kc][1], qh[kc][2], qh[kc][3], bh2, bh3);
            }
        }

        // ---- p = ex2.f16x2(s'), packed directly into PV A-fragment regs ----
        uint32_t p01[16], p23[16];
        #pragma unroll
        for (int i = 0; i < 16; i++) {
            p01[i] = ex2h2(packhf(s0[i], s1[i]));
            p23[i] = ex2h2(packhf(s2[i], s3[i]));
        }

        // ---- O += P V ; l += P @ ones (tensor-pipe row sums) ----
        #pragma unroll
        for (int kc = 0; kc < 8; kc++) {
            uint32_t ph0 = p01[2*kc], ph1 = p23[2*kc];
            uint32_t ph2 = p01[2*kc+1], ph3 = p23[2*kc+1];
            mma16816h(la0, la1, la2, la3, ph0, ph1, ph2, ph3, ONESH2, ONESH2);
            #pragma unroll
            for (int ncp = 0; ncp < 4; ncp++) {
                uint32_t ad = bufb + OFF_VHI + (uint32_t)(kc * 16 + krv) * 128
                            + (((2 * ncp + vbit) ^ s7) << 4);
                uint32_t bh0, bh1, bh2, bh3;
                ldsm4t(bh0, bh1, bh2, bh3, ad);
                int n = 2 * ncp;
                mma16816h(o0[n], o1[n], o2[n], o3[n], ph0, ph1, ph2, ph3, bh0, bh1);
                mma16816h(o0[n+1], o1[n+1], o2[n+1], o3[n+1], ph0, ph1, ph2, ph3, bh2, bh3);
            }
        }
    }

    // la0 = full row sum (row r), la2 = row r+8 — identical across the quad.
    const float il0 = 1.0f / la0, il1 = 1.0f / la2;
    const int r  = lane >> 2;
    const int c2 = (lane & 3) * 2;
    float2* out2 = (float2*)out;
    #pragma unroll
    for (int nc = 0; nc < 8; nc++) {
        size_t i_lo = ((size_t)(qbase + wrow + r)     * 64 + 8 * nc + c2) >> 1;
        size_t i_hi = ((size_t)(qbase + wrow + r + 8) * 64 + 8 * nc + c2) >> 1;
        out2[i_lo] = make_float2(o0[nc] * il0, o1[nc] * il0);
        out2[i_hi] = make_float2(o2[nc] * il1, o3[nc] * il1);
    }
}

// ===========================================================================
// Launch
// ===========================================================================
extern "C" void kernel_launch(void* const* d_in, const int* in_sizes, int n_in,
                              void* d_out, int out_size)
{
    const float* X  = (const float*)d_in[0];
    const float* Wq = (const float*)d_in[1];
    const float* Wk = (const float*)d_in[2];
    const float* Wv = (const float*)d_in[3];
    float* out = (float*)d_out;

    conv_xw_kernel<<<2096, 256>>>(X, Wq, Wk, Wv);

    cudaFuncSetAttribute(proj_ln_kernel, cudaFuncAttributeMaxDynamicSharedMemorySize, PROJ_SMEM);
    proj_ln_kernel<<<NROWS / 128, 256, PROJ_SMEM>>>();

    cudaFuncSetAttribute(attn_mma_kernel, cudaFuncAttributeMaxDynamicSharedMemorySize, ATTN_SMEM);
    attn_mma_kernel<<<NROWS / 128, 256, ATTN_SMEM>>>(out);
}

// round 16
// speedup vs baseline: 1.1522x; 1.1522x over previous
#include <cuda_runtime.h>
#include <cuda_fp16.h>
#include <math.h>
#include <stdint.h>

// Problem shape: B=4, S=4096, D=1024, H=64
#define B_ 4
#define S_ 4096
#define D_ 1024
#define H_ 64
#define NROWS (B_ * S_)   // 16384

// Attention operands (fp16). Q pre-scaled by C = 0.125*log2(e) so the QK mma
// directly emits the exp2 argument. K, V unscaled.
__device__ __half g_qh[NROWS * H_];
__device__ __half g_kh[NROWS * H_];
__device__ __half g_vh[NROWS * H_];
// Pre-converted W (fp16), per-64k-chunk swizzled tiles (8KB per chunk).
__device__ __half g_wh[3][D_ * H_];

#define EXPC 0.18033688f   // 0.125 * log2(e)

// ===========================================================================
// helpers
// ===========================================================================
__device__ __forceinline__ uint32_t smem_u32(const void* p) {
    uint32_t a;
    asm("{ .reg .u64 t; cvta.to.shared.u64 t, %1; cvt.u32.u64 %0, t; }" : "=r"(a) : "l"(p));
    return a;
}
__device__ __forceinline__ uint32_t packhf(float a, float b) {
    uint32_t r;
    asm("cvt.rn.f16x2.f32 %0, %2, %1;" : "=r"(r) : "f"(a), "f"(b));
    return r;
}
__device__ __forceinline__ uint32_t ex2h2(uint32_t x) {
    uint32_t r;
    asm("ex2.approx.f16x2 %0, %1;" : "=r"(r) : "r"(x));
    return r;
}

__device__ __forceinline__ void ldsm4(uint32_t& r0, uint32_t& r1, uint32_t& r2, uint32_t& r3, uint32_t addr) {
    asm volatile("ldmatrix.sync.aligned.m8n8.x4.shared.b16 {%0,%1,%2,%3}, [%4];"
        : "=r"(r0), "=r"(r1), "=r"(r2), "=r"(r3) : "r"(addr));
}
__device__ __forceinline__ void ldsm4t(uint32_t& r0, uint32_t& r1, uint32_t& r2, uint32_t& r3, uint32_t addr) {
    asm volatile("ldmatrix.sync.aligned.m8n8.x4.trans.shared.b16 {%0,%1,%2,%3}, [%4];"
        : "=r"(r0), "=r"(r1), "=r"(r2), "=r"(r3) : "r"(addr));
}
__device__ __forceinline__ void mma16816h(float& d0, float& d1, float& d2, float& d3,
                                           uint32_t a0, uint32_t a1, uint32_t a2, uint32_t a3,
                                           uint32_t b0, uint32_t b1) {
    asm volatile("mma.sync.aligned.m16n8k16.row.col.f32.f16.f16.f32 "
        "{%0,%1,%2,%3}, {%4,%5,%6,%7}, {%8,%9}, {%0,%1,%2,%3};"
        : "+f"(d0), "+f"(d1), "+f"(d2), "+f"(d3)
        : "r"(a0), "r"(a1), "r"(a2), "r"(a3), "r"(b0), "r"(b1));
}

#define CP_ASYNC16(dst, src) \
    asm volatile("cp.async.cg.shared.global [%0], [%1], 16;" :: "r"(dst), "l"(src))
#define CP_COMMIT() asm volatile("cp.async.commit_group;" ::: "memory")
#define CP_WAIT(n)  asm volatile("cp.async.wait_group %0;" :: "n"(n) : "memory")

// ===========================================================================
// Kernel 0: convert W matrices to fp16, per-chunk swizzled tiles (R13).
// ===========================================================================
__global__ __launch_bounds__(256) void split_w_kernel(
    const float* __restrict__ Wq, const float* __restrict__ Wk, const float* __restrict__ Wv)
{
    const int ck = blockIdx.x, m = blockIdx.y, tid = threadIdx.x;
    const float4* W4 = (const float4*)((m == 0) ? Wq : ((m == 1) ? Wk : Wv));
    char* hiB = (char*)g_wh[m] + ck * 8192;
    #pragma unroll
    for (int j = 0; j < 4; j++) {
        int f = tid + j * 256;
        int r = f >> 4, c4 = f & 15;
        float4 v = W4[(size_t)(ck * 64 + r) * 16 + c4];
        uint32_t so = (uint32_t)(r * 128 + (((c4 >> 1) ^ (r & 7)) << 4) + (c4 & 1) * 8);
        *(uint32_t*)(hiB + so)     = packhf(v.x, v.y);
        *(uint32_t*)(hiB + so + 4) = packhf(v.z, v.w);
    }
}

// ===========================================================================
// Kernel 1: fused QKV projection + LayerNorm, single-pass fp16 (R13 verbatim).
// ===========================================================================
#define P_XH  0
#define P_WH  16384
#define P_WSTRIDE 8192
#define PROJ_SMEM (16384 + 3 * 8192)

__global__ __launch_bounds__(256) void proj_ln_kernel(const float* __restrict__ X)
{
    extern __shared__ char smem[];
    const uint32_t sb = smem_u32(smem);
    const int tid  = threadIdx.x;
    const int warp = tid >> 5, lane = tid & 31;
    const int wrow = warp * 16;
    const int mt   = blockIdx.x;

    float a0[3][8], a1[3][8], a2[3][8], a3[3][8];
    #pragma unroll
    for (int m = 0; m < 3; m++)
        #pragma unroll
        for (int nc = 0; nc < 8; nc++) { a0[m][nc]=0.f; a1[m][nc]=0.f; a2[m][nc]=0.f; a3[m][nc]=0.f; }

    const float4* X4 = (const float4*)X;

    const int arow = wrow + (lane & 15);
    const int as7  = arow & 7;
    const int abit = lane >> 4;
    const int krv  = lane & 15;
    const int vbit = lane >> 4;
    const int s7   = lane & 7;

    float4 xv[8];
    #pragma unroll
    for (int j = 0; j < 8; j++) {
        int f = tid + j * 256;
        xv[j] = X4[(size_t)(mt * 128 + (f >> 4)) * 256 + (f & 15)];
    }

    for (int kk = 0; kk < D_; kk += 64) {
        __syncthreads();

        #pragma unroll
        for (int m = 0; m < 3; m++) {
            const char* srcH = (const char*)g_wh[m] + (kk >> 6) * 8192;
            #pragma unroll
            for (int j = 0; j < 2; j++) {
                int f16 = (tid + j * 256) * 16;
                CP_ASYNC16(sb + P_WH + (uint32_t)(m * P_WSTRIDE) + f16, srcH + f16);
            }
        }
        CP_COMMIT();

        #pragma unroll
        for (int j = 0; j < 8; j++) {
            int f = tid + j * 256;
            int r = f >> 4, c4 = f & 15;
            float4 v = xv[j];
            uint32_t so = (uint32_t)(r * 128 + (((c4 >> 1) ^ (r & 7)) << 4) + (c4 & 1) * 8);
            *(uint32_t*)(smem + P_XH + so)     = packhf(v.x, v.y);
            *(uint32_t*)(smem + P_XH + so + 4) = packhf(v.z, v.w);
        }
        if (kk + 64 < D_) {
            #pragma unroll
            for (int j = 0; j < 8; j++) {
                int f = tid + j * 256;
                xv[j] = X4[(size_t)(mt * 128 + (f >> 4)) * 256 + ((kk + 64) >> 2) + (f & 15)];
            }
        }
        CP_WAIT(0);
        __syncthreads();

        uint32_t xh[4][4];
        #pragma unroll
        for (int kc = 0; kc < 4; kc++) {
            int c16 = 2 * kc + abit;
            uint32_t ad = sb + P_XH + (uint32_t)(arow * 128) + ((c16 ^ as7) << 4);
            ldsm4(xh[kc][0], xh[kc][1], xh[kc][2], xh[kc][3], ad);
        }

        #pragma unroll
        for (int m = 0; m < 3; m++) {
            uint32_t wbase = sb + P_WH + (uint32_t)(m * P_WSTRIDE);
            #pragma unroll
            for (int kc = 0; kc < 4; kc++) {
                #pragma unroll
                for (int ncp = 0; ncp < 4; ncp++) {
                    uint32_t ad = wbase + (uint32_t)((kc * 16 + krv) * 128)
                                + (((2 * ncp + vbit) ^ s7) << 4);
                    uint32_t bh0, bh1, bh2, bh3;
                    ldsm4t(bh0, bh1, bh2, bh3, ad);
                    int n = 2 * ncp;
                    mma16816h(a0[m][n], a1[m][n], a2[m][n], a3[m][n],
                              xh[kc][0], xh[kc][1], xh[kc][2], xh[kc][3], bh0, bh1);
                    mma16816h(a0[m][n+1], a1[m][n+1], a2[m][n+1], a3[m][n+1],
                              xh[kc][0], xh[kc][1], xh[kc][2], xh[kc][3], bh2, bh3);
                }
            }
        }
    }

    const int rA = mt * 128 + wrow + (lane >> 2);
    const int rB = rA + 8;

    #pragma unroll
    for (int m = 0; m < 3; m++) {
        float mu0 = 0.f, mu1 = 0.f, rs0 = 1.f, rs1 = 1.f;
        if (m < 2) {
            float sum0 = 0.f, sum1 = 0.f;
            #pragma unroll
            for (int nc = 0; nc < 8; nc++) {
                sum0 += a0[m][nc] + a1[m][nc];
                sum1 += a2[m][nc] + a3[m][nc];
            }
            sum0 += __shfl_xor_sync(0xffffffffu, sum0, 1);
            sum0 += __shfl_xor_sync(0xffffffffu, sum0, 2);
            sum1 += __shfl_xor_sync(0xffffffffu, sum1, 1);
            sum1 += __shfl_xor_sync(0xffffffffu, sum1, 2);
            mu0 = sum0 * (1.0f / 64.0f);
            mu1 = sum1 * (1.0f / 64.0f);
            float v0 = 0.f, v1 = 0.f;
            #pragma unroll
            for (int nc = 0; nc < 8; nc++) {
                float d00 = a0[m][nc] - mu0, d01 = a1[m][nc] - mu0;
                float d10 = a2[m][nc] - mu1, d11 = a3[m][nc] - mu1;
                v0 += d00 * d00 + d01 * d01;
                v1 += d10 * d10 + d11 * d11;
            }
            v0 += __shfl_xor_sync(0xffffffffu, v0, 1);
            v0 += __shfl_xor_sync(0xffffffffu, v0, 2);
            v1 += __shfl_xor_sync(0xffffffffu, v1, 1);
            v1 += __shfl_xor_sync(0xffffffffu, v1, 2);
            rs0 = rsqrtf(v0 * (1.0f / 64.0f) + 1e-5f);
            rs1 = rsqrtf(v1 * (1.0f / 64.0f) + 1e-5f);
        }
        if (m == 0) { rs0 *= EXPC; rs1 *= EXPC; }

        uint32_t* g32 = (uint32_t*)((m == 0) ? g_qh : ((m == 1) ? g_kh : g_vh));
        #pragma unroll
        for (int nc = 0; nc < 8; nc++) {
            uint32_t hA = packhf((a0[m][nc] - mu0) * rs0, (a1[m][nc] - mu0) * rs0);
            uint32_t hB = packhf((a2[m][nc] - mu1) * rs1, (a3[m][nc] - mu1) * rs1);
            size_t iA = (size_t)rA * 32 + nc * 4 + (lane & 3);
            size_t iB = (size_t)rB * 32 + nc * 4 + (lane & 3);
            g32[iA] = hA;
            g32[iB] = hB;
        }
    }
}

// ===========================================================================
// Kernel 2: flash attention, 512 threads (16 warps = 8 row-groups x 2
// key-halves) for 4 warps/SMSP at UNCHANGED per-SM memory traffic.
// Streamed softmax per 16-key chunk (low registers). Fixed-reference
// softmax, ex2.f16x2, l via ones-mma. Key-half partials combined in smem.
// ===========================================================================
#define OFF_KHI 0
#define OFF_VHI 16384
#define TB      32768
#define NT      (S_ / 128)
#define ATTN_SMEM (2 * TB)
#define ONESH2  0x3C003C00u   // fp16x2 {1.0, 1.0}
#define EP_OST  68            // epilogue row stride (floats)
#define EP_LB   34816         // l partials base (after 8 x 4352B o regions)

__global__ __launch_bounds__(512) void attn_mma_kernel(float* __restrict__ out)
{
    extern __shared__ char smem[];
    const uint32_t sb = smem_u32(smem);
    const int tid  = threadIdx.x;
    const int warp = tid >> 5, lane = tid & 31;
    const int wg   = warp & 7;            // row group (16 q rows)
    const int half = warp >> 3;           // key half (64 keys of 128-key tile)
    const int wrow = wg * 16;
    const int keyoff = half * 64;

    const int qbase = blockIdx.x * 128;
    const int b     = qbase / S_;

    // ---- stage Q into buf0 (K area), grab A fragments ----
    {
        const uint4* qh4 = (const uint4*)((const char*)g_qh + (size_t)qbase * 128);
        #pragma unroll
        for (int j = 0; j < 2; j++) {
            int f = tid + j * 512;               // 0..1023 uint4
            int r = f >> 3, c = f & 7;
            uint32_t so = r * 128 + ((c ^ (r & 7)) << 4);
            *(uint4*)(smem + OFF_KHI + so) = qh4[f];
        }
    }
    __syncthreads();

    uint32_t qf[4][4];
    {
        int arow = wrow + (lane & 15);
        int as7  = arow & 7;
        #pragma unroll
        for (int kc = 0; kc < 4; kc++) {
            int c16 = 2 * kc + (lane >> 4);
            uint32_t ad = sb + OFF_KHI + arow * 128 + ((c16 ^ as7) << 4);
            ldsm4(qf[kc][0], qf[kc][1], qf[kc][2], qf[kc][3], ad);
        }
    }
    __syncthreads();

    const char* khB = (const char*)g_kh + (size_t)(b * S_) * 128;
    const char* vhB = (const char*)g_vh + (size_t)(b * S_) * 128;

    // prefetch tile 0 -> buf 0
    {
        #pragma unroll
        for (int j = 0; j < 2; j++) {
            int f = tid + j * 512;
            int r = f >> 3, c = f & 7;
            uint32_t so = r * 128 + ((c ^ (r & 7)) << 4);
            int gs = f * 16;
            CP_ASYNC16(sb + OFF_KHI + so, khB + gs);
            CP_ASYNC16(sb + OFF_VHI + so, vhB + gs);
        }
        CP_COMMIT();
    }

    float o0[8], o1[8], o2[8], o3[8];
    float la0 = 0.f, la1 = 0.f, la2 = 0.f, la3 = 0.f;
    #pragma unroll
    for (int i = 0; i < 8; i++) { o0[i] = 0.f; o1[i] = 0.f; o2[i] = 0.f; o3[i] = 0.f; }

    const int s7   = lane & 7;
    const int krq  = (lane & 7) + ((lane >> 4) << 3);
    const int cbit = (lane >> 3) & 1;
    const int krv  = lane & 15;
    const int vbit = lane >> 4;

    for (int kt = 0; kt < NT; kt++) {
        __syncthreads();

        if (kt + 1 < NT) {
            uint32_t dst = sb + ((kt + 1) & 1) * TB;
            size_t gb = (size_t)((kt + 1) * 128) * 128;
            #pragma unroll
            for (int j = 0; j < 2; j++) {
                int f = tid + j * 512;
                int r = f >> 3, c = f & 7;
                uint32_t so = r * 128 + ((c ^ (r & 7)) << 4);
                size_t gs = gb + f * 16;
                CP_ASYNC16(dst + OFF_KHI + so, khB + gs);
                CP_ASYNC16(dst + OFF_VHI + so, vhB + gs);
            }
            CP_COMMIT();
            CP_WAIT(1);
        } else {
            CP_WAIT(0);
        }
        __syncthreads();

        const uint32_t bufb = sb + (kt & 1) * TB;

        // ---- streamed: per 16-key chunk QK -> ex2 -> ones -> PV ----
        #pragma unroll
        for (int kc2 = 0; kc2 < 4; kc2++) {
            float t0[2], t1[2], t2[2], t3[2];
            t0[0]=0.f; t1[0]=0.f; t2[0]=0.f; t3[0]=0.f;
            t0[1]=0.f; t1[1]=0.f; t2[1]=0.f; t3[1]=0.f;
            #pragma unroll
            for (int kcd = 0; kcd < 4; kcd++) {
                uint32_t ad = bufb + OFF_KHI
                            + (uint32_t)((keyoff + kc2 * 16 + krq) * 128)
                            + (((2 * kcd + cbit) ^ s7) << 4);
                uint32_t bh0, bh1, bh2, bh3;
                ldsm4(bh0, bh1, bh2, bh3, ad);
                mma16816h(t0[0], t1[0], t2[0], t3[0],
                          qf[kcd][0], qf[kcd][1], qf[kcd][2], qf[kcd][3], bh0, bh1);
                mma16816h(t0[1], t1[1], t2[1], t3[1],
                          qf[kcd][0], qf[kcd][1], qf[kcd][2], qf[kcd][3], bh2, bh3);
            }
            uint32_t ph0 = ex2h2(packhf(t0[0], t1[0]));
            uint32_t ph1 = ex2h2(packhf(t2[0], t3[0]));
            uint32_t ph2 = ex2h2(packhf(t0[1], t1[1]));
            uint32_t ph3 = ex2h2(packhf(t2[1], t3[1]));
            mma16816h(la0, la1, la2, la3, ph0, ph1, ph2, ph3, ONESH2, ONESH2);
            #pragma unroll
            for (int ncp = 0; ncp < 4; ncp++) {
                uint32_t ad = bufb + OFF_VHI
                            + (uint32_t)((keyoff + kc2 * 16 + krv) * 128)
                            + (((2 * ncp + vbit) ^ s7) << 4);
                uint32_t bh0, bh1, bh2, bh3;
                ldsm4t(bh0, bh1, bh2, bh3, ad);
                int n = 2 * ncp;
                mma16816h(o0[n], o1[n], o2[n], o3[n], ph0, ph1, ph2, ph3, bh0, bh1);
                mma16816h(o0[n+1], o1[n+1], o2[n+1], o3[n+1], ph0, ph1, ph2, ph3, bh2, bh3);
            }
        }
    }

    // ---- combine key-halves via smem (reuse tile buffers) ----
    const int r  = lane >> 2;
    const int c2 = (lane & 3) * 2;

    __syncthreads();   // all warps done reading K/V smem

    if (half == 1) {
        float* ob = (float*)(smem + wg * 4352);
        #pragma unroll
        for (int nc = 0; nc < 8; nc++) {
            int col = 8 * nc + c2;
            *(float2*)&ob[r * EP_OST + col]       = make_float2(o0[nc], o1[nc]);
            *(float2*)&ob[(r + 8) * EP_OST + col] = make_float2(o2[nc], o3[nc]);
        }
        if ((lane & 3) == 0) {
            float* lb = (float*)(smem + EP_LB + wg * 64);
            lb[r]     = la0;
            lb[r + 8] = la2;
        }
    }
    __syncthreads();

    if (half == 0) {
        const float* ob = (const float*)(smem + wg * 4352);
        const float* lb = (const float*)(smem + EP_LB + wg * 64);
        float il0 = 1.0f / (la0 + lb[r]);
        float il1 = 1.0f / (la2 + lb[r + 8]);
        float2* out2 = (float2*)out;
        #pragma unroll
        for (int nc = 0; nc < 8; nc++) {
            int col = 8 * nc + c2;
            float2 p = *(const float2*)&ob[r * EP_OST + col];
            float2 q = *(const float2*)&ob[(r + 8) * EP_OST + col];
            size_t i_lo = ((size_t)(qbase + wrow + r)     * 64 + col) >> 1;
            size_t i_hi = ((size_t)(qbase + wrow + r + 8) * 64 + col) >> 1;
            out2[i_lo] = make_float2((o0[nc] + p.x) * il0, (o1[nc] + p.y) * il0);
            out2[i_hi] = make_float2((o2[nc] + q.x) * il1, (o3[nc] + q.y) * il1);
        }
    }
}

// ===========================================================================
// Launch
// ===========================================================================
extern "C" void kernel_launch(void* const* d_in, const int* in_sizes, int n_in,
                              void* d_out, int out_size)
{
    const float* X  = (const float*)d_in[0];
    const float* Wq = (const float*)d_in[1];
    const float* Wk = (const float*)d_in[2];
    const float* Wv = (const float*)d_in[3];
    float* out = (float*)d_out;

    dim3 gw(16, 3);
    split_w_kernel<<<gw, 256>>>(Wq, Wk, Wv);

    cudaFuncSetAttribute(proj_ln_kernel, cudaFuncAttributeMaxDynamicSharedMemorySize, PROJ_SMEM);
    proj_ln_kernel<<<NROWS / 128, 256, PROJ_SMEM>>>(X);

    cudaFuncSetAttribute(attn_mma_kernel, cudaFuncAttributeMaxDynamicSharedMemorySize, ATTN_SMEM);
    attn_mma_kernel<<<NROWS / 128, 512, ATTN_SMEM>>>(out);
}